// round 7
// baseline (speedup 1.0000x reference)
#include <cuda_runtime.h>
#include <math.h>

// Problem constants
#define BB   32
#define SSL  1024
#define SQQ  32
#define NNN  128
#define DINN 128
#define HHH  256
#define AAA  100
#define OOO  2000
#define G3H  768
#define FEAT 1794   // 7*H + 2

// ---------------- scratch offsets (floats) in one big device buffer ----------
#define OFF_GI    0UL          // 1024*768*32 = 25165824
#define OFF_GIQ   25165824UL   // 32*768*32   =   786432
#define OFF_H     25952256UL   // 2*256*32    =    16384  (ping-pong h, [pp][k][b])
#define OFF_COUT  25968640UL   // 1024*32*256 =  8388608  ([t][b][k])
#define OFF_QOUT  34357248UL   // 32*32*256   =   262144
#define OFF_QH    34619392UL   // 32*256
#define OFF_HTC   34627584UL   // 32*256 (unused final h of context GRU)
#define OFF_CSEL  34635776UL   // 32*128*256
#define OFF_CW    35684352UL   // 32*128*256
#define OFF_DOTQ  36732928UL   // 4096
#define OFF_DOTM  36737024UL   // 4096
#define OFF_T0    36741120UL   // 4096*100
#define OFF_M     37150720UL   // 32*256
#define OFF_SC    37158912UL   // 4096
#define OFF_P     37163008UL   // 4096
#define OFF_E     37167104UL   // 32*256
#define OFF_MSQ   37175296UL   // 32*256
#define OFF_Y     37183488UL   // 32*2000 = 64000
#define OFF_W1T   37247488UL   // 1794*128 = 229632
#define OFF_BT    37477120UL   // 32*100 = 3200
#define TOTALF    37480320UL

__device__ __align__(16) float g_buf[TOTALF];

__device__ unsigned g_bar_cnt = 0;
__device__ volatile unsigned g_bar_gen = 0;

// ---------------- grid barrier (all blocks co-resident) ----------------------
__device__ __forceinline__ void grid_barrier() {
    __syncthreads();
    if (threadIdx.x == 0) {
        unsigned gen = g_bar_gen;
        __threadfence();
        if (atomicAdd(&g_bar_cnt, 1) == gridDim.x - 1) {
            g_bar_cnt = 0;
            __threadfence();
            g_bar_gen = gen + 1;
        } else {
            while (g_bar_gen == gen) {
#if __CUDA_ARCH__ >= 700
                __nanosleep(32);
#endif
            }
        }
        __threadfence();
    }
    __syncthreads();
}

// ---------------- gi = x @ w_ih^T + b_ih  ->  out[t][row][b] -----------------
__global__ void __launch_bounds__(256) gi_kernel(
    const float* __restrict__ x, const float* __restrict__ w,
    const float* __restrict__ bias, float* __restrict__ out, int S)
{
    const int t = blockIdx.x;
    __shared__ float xs[DINN][33];
    for (int idx = threadIdx.x; idx < BB * DINN; idx += 256) {
        int b = idx >> 7, k = idx & 127;
        xs[k][b] = x[(b * S + t) * DINN + k];
    }
    __syncthreads();
    const int b  = threadIdx.x & 31;
    const int w0 = threadIdx.x >> 5;
    for (int r = w0; r < G3H; r += 8) {
        const float4* wr = (const float4*)(w + r * DINN);
        float a0 = 0.f, a1 = 0.f, a2 = 0.f, a3 = 0.f;
        #pragma unroll
        for (int k4 = 0; k4 < DINN / 4; ++k4) {
            float4 wv = __ldg(wr + k4);
            int k = k4 * 4;
            a0 += wv.x * xs[k + 0][b];
            a1 += wv.y * xs[k + 1][b];
            a2 += wv.z * xs[k + 2][b];
            a3 += wv.w * xs[k + 3][b];
        }
        out[((size_t)t * G3H + r) * BB + b] = bias[r] + (a0 + a1) + (a2 + a3);
    }
}

// ---------------- h init: hbuf[k][b] = st[b][k] ------------------------------
__global__ void inith_kernel(const float* __restrict__ st, float* __restrict__ hbuf)
{
    hbuf[threadIdx.x * BB + blockIdx.x] = st[blockIdx.x * HHH + threadIdx.x];
}

// ---------------- persistent GRU recurrence (128 blocks x 192 threads) -------
__global__ void __launch_bounds__(192, 1) rec_kernel(
    const float* __restrict__ gi, const float* __restrict__ whh,
    const float* __restrict__ bhh, int S,
    float* __restrict__ hbuf, float* __restrict__ cout,
    float* __restrict__ finalh)
{
    const int j = blockIdx.x;            // 0..127 -> owns h cols 2j, 2j+1
    const int c0 = 2 * j;
    const int tid = threadIdx.x;
    const int wid = tid >> 5, lane = tid & 31;

    __shared__ float ws[6][HHH];
    __shared__ float hs[HHH][BB];
    __shared__ float ghs[6][BB];
    __shared__ float gis[6][BB];
    __shared__ float bsh[6];

    const int grow = (wid >> 1) * HHH + c0 + (wid & 1);   // row in [0,768)
    for (int k = lane; k < HHH; k += 32) ws[wid][k] = whh[grow * HHH + k];
    if (lane == 0) bsh[wid] = bhh[grow];
    __syncthreads();

    int pp = 0;
    for (int t = 0; t < S; ++t) {
        gis[wid][lane] = __ldg(&gi[((size_t)t * G3H + grow) * BB + lane]);
        const float4* src = (const float4*)(hbuf + pp * (HHH * BB));
        float4* dst = (float4*)&hs[0][0];
        #pragma unroll
        for (int i = 0; i < 11; ++i) {
            int idx = tid + i * 192;
            if (idx < (HHH * BB) / 4) dst[idx] = __ldcg(src + idx);
        }
        __syncthreads();

        const float4* wr = (const float4*)&ws[wid][0];
        float a0 = 0.f, a1 = 0.f, a2 = 0.f, a3 = 0.f;
        #pragma unroll
        for (int k4 = 0; k4 < HHH / 4; ++k4) {
            float4 w = wr[k4];
            int k = k4 * 4;
            a0 += w.x * hs[k + 0][lane];
            a1 += w.y * hs[k + 1][lane];
            a2 += w.z * hs[k + 2][lane];
            a3 += w.w * hs[k + 3][lane];
        }
        ghs[wid][lane] = (a0 + a1) + (a2 + a3) + bsh[wid];
        __syncthreads();

        if (tid < 64) {
            int cc = tid >> 5, b = tid & 31;
            int col = c0 + cc;
            float ir  = gis[cc][b],     hr = ghs[cc][b];
            float iz  = gis[2 + cc][b], hz = ghs[2 + cc][b];
            float in_ = gis[4 + cc][b], hn = ghs[4 + cc][b];
            float rg = 1.f / (1.f + expf(-(ir + hr)));
            float zg = 1.f / (1.f + expf(-(iz + hz)));
            float ng = tanhf(in_ + rg * hn);
            float hold = hs[col][b];
            float hnew = (1.f - zg) * ng + zg * hold;
            hbuf[(pp ^ 1) * (HHH * BB) + col * BB + b] = hnew;
            cout[((size_t)t * BB + b) * HHH + col] = hnew;
            if (t == S - 1) finalh[b * HHH + col] = hnew;
        }
        grid_barrier();
        pp ^= 1;
    }
}

// ---------------- transpose att_w1 -> w1t[f][a] padded to 128 ----------------
__global__ void w1t_kernel(const float* __restrict__ w1, float* __restrict__ w1t)
{
    int idx = blockIdx.x * 256 + threadIdx.x;
    if (idx >= FEAT * 128) return;
    int f = idx >> 7, a = idx & 127;
    w1t[idx] = (a < AAA) ? w1[a * FEAT + f] : 0.f;
}

// ---------------- gather c_sel + cw = c_sel @ att_weight ---------------------
__global__ void __launch_bounds__(256) cwgather_kernel(
    const float* __restrict__ cout, const int* __restrict__ cindex,
    const float* __restrict__ attw, float* __restrict__ csel, float* __restrict__ cw)
{
    const int r0 = blockIdx.x * 16;
    const int b  = r0 >> 7;
    const int tid = threadIdx.x;
    __shared__ float cs[16][HHH];
    __shared__ int ti[16];
    if (tid < 16) ti[tid] = cindex[b * NNN + ((r0 + tid) & 127)];
    __syncthreads();
    for (int idx = tid; idx < 16 * HHH; idx += 256) {
        int r = idx >> 8, k = idx & 255;
        float v = cout[((size_t)ti[r] * BB + b) * HHH + k];
        cs[r][k] = v;
        csel[(size_t)(r0 + r) * HHH + k] = v;
    }
    __syncthreads();
    float acc[16];
    #pragma unroll
    for (int r = 0; r < 16; ++r) acc[r] = 0.f;
    const int jcol = tid;
    for (int k = 0; k < HHH; ++k) {
        float wk = attw[k * HHH + jcol];
        #pragma unroll
        for (int r = 0; r < 16; ++r) acc[r] += cs[r][k] * wk;
    }
    #pragma unroll
    for (int r = 0; r < 16; ++r) cw[(size_t)(r0 + r) * HHH + jcol] = acc[r];
}

// ---------------- per-row dot with per-b vector ------------------------------
__global__ void dot_kernel(const float* __restrict__ mat, const float* __restrict__ vec,
                           float* __restrict__ out)
{
    const int row = blockIdx.x;
    const int b = row >> 7;
    const int tid = threadIdx.x;   // 64 threads
    const float4* mr = (const float4*)(mat + (size_t)row * HHH);
    const float4* vr = (const float4*)(vec + b * HHH);
    float4 a = mr[tid], v = vr[tid];
    float s = a.x * v.x + a.y * v.y + a.z * v.z + a.w * v.w;
    for (int o = 16; o; o >>= 1) s += __shfl_xor_sync(0xffffffffu, s, o);
    __shared__ float sm[2];
    if ((tid & 31) == 0) sm[tid >> 5] = s;
    __syncthreads();
    if (tid == 0) out[row] = sm[0] + sm[1];
}

// ---------------- bterm[b][a] = (b1?) + v[b] . w1[a][off:off+256] ------------
__global__ void bterm_kernel(const float* __restrict__ v, const float* __restrict__ w1,
                             const float* __restrict__ b1, int off, float* __restrict__ out)
{
    const int b = blockIdx.x, a = threadIdx.x;
    if (a >= AAA) return;
    float acc = b1 ? b1[a] : 0.f;
    const float* wr = w1 + (size_t)a * FEAT + off;
    const float* vb = v + b * HHH;
    for (int k = 0; k < HHH; ++k) acc += vb[k] * wr[k];
    out[b * AAA + a] = acc;
}

// ---------------- attention projection (T0 precompute or hop+score) ----------
template <bool USEC, bool SCORE>
__global__ void __launch_bounds__(128) attproj_kernel(
    const float* __restrict__ csel, const float* __restrict__ vvec,
    const float* __restrict__ base, const float* __restrict__ dotv,
    const float* __restrict__ w1t, const float* __restrict__ bterm,
    int o2, int o3, int dotcol,
    const float* __restrict__ w2, const float* __restrict__ b2,
    float* __restrict__ outT0, float* __restrict__ outScores)
{
    const int r0 = blockIdx.x * 16;
    const int b  = r0 >> 7;
    const int tid = threadIdx.x;
    __shared__ float cs[16][HHH];
    __shared__ float vs[HHH];
    __shared__ float red[4];
    for (int idx = tid; idx < 16 * HHH; idx += 128)
        cs[idx >> 8][idx & 255] = csel[(size_t)(r0 + (idx >> 8)) * HHH + (idx & 255)];
    for (int idx = tid; idx < HHH; idx += 128) vs[idx] = vvec[b * HHH + idx];
    __syncthreads();

    const int a = tid;
    const bool va = a < AAA;
    float bt = va ? bterm[b * AAA + a] : 0.f;
    float wd = w1t[dotcol * 128 + a];
    float acc[16];
    #pragma unroll
    for (int r = 0; r < 16; ++r) {
        float v0 = bt + dotv[r0 + r] * wd;
        if (SCORE && va) v0 += base[(size_t)(r0 + r) * AAA + a];
        acc[r] = v0;
    }
    for (int k = 0; k < HHH; ++k) {
        float f1 = USEC ? w1t[k * 128 + a] : 0.f;
        float f2 = w1t[(o2 + k) * 128 + a];
        float f3 = w1t[(o3 + k) * 128 + a];
        float vk = vs[k];
        #pragma unroll
        for (int r = 0; r < 16; ++r) {
            float c = cs[r][k];
            acc[r] += (c * vk) * f2 + fabsf(c - vk) * f3;
            if (USEC) acc[r] += c * f1;
        }
    }
    if (!SCORE) {
        if (va) {
            #pragma unroll
            for (int r = 0; r < 16; ++r) outT0[(size_t)(r0 + r) * AAA + a] = acc[r];
        }
    } else {
        float w2a = va ? w2[a] : 0.f;
        for (int r = 0; r < 16; ++r) {
            float ctr = va ? tanhf(acc[r]) * w2a : 0.f;
            for (int o = 16; o; o >>= 1) ctr += __shfl_xor_sync(0xffffffffu, ctr, o);
            if ((tid & 31) == 0) red[tid >> 5] = ctr;
            __syncthreads();
            if (tid == 0) outScores[r0 + r] = red[0] + red[1] + red[2] + red[3] + b2[0];
            __syncthreads();
        }
    }
}

// ---------------- masked softmax over N=128 ----------------------------------
__global__ void softmaxN_kernel(const float* __restrict__ scores, const int* __restrict__ lenc,
                                float* __restrict__ p, float* __restrict__ attout)
{
    const int b = blockIdx.x, n = threadIdx.x;
    const int lc = lenc[b];
    __shared__ float red[4];
    float s = (n < lc) ? scores[b * NNN + n] : -1e30f;
    float m = s;
    for (int o = 16; o; o >>= 1) m = fmaxf(m, __shfl_xor_sync(0xffffffffu, m, o));
    if ((n & 31) == 0) red[n >> 5] = m;
    __syncthreads();
    m = fmaxf(fmaxf(red[0], red[1]), fmaxf(red[2], red[3]));
    __syncthreads();
    float ev = (n < lc) ? expf(s - m) : 0.f;
    float sum = ev;
    for (int o = 16; o; o >>= 1) sum += __shfl_xor_sync(0xffffffffu, sum, o);
    if ((n & 31) == 0) red[n >> 5] = sum;
    __syncthreads();
    sum = red[0] + red[1] + red[2] + red[3];
    float pv = ev / sum;
    p[b * NNN + n] = pv;
    attout[b * NNN + n] = pv;
}

// ---------------- e[b][k] = sum_n csel[b][n][k] * p[b][n] --------------------
__global__ void __launch_bounds__(256) e_kernel(const float* __restrict__ csel,
                                                const float* __restrict__ p,
                                                float* __restrict__ e)
{
    const int b = blockIdx.x, k = threadIdx.x;
    __shared__ float ps[NNN];
    if (k < NNN) ps[k] = p[b * NNN + k];
    __syncthreads();
    float acc = 0.f;
    for (int n = 0; n < NNN; ++n)
        acc += csel[(size_t)((b << 7) + n) * HHH + k] * ps[n];
    e[b * HHH + k] = acc;
}

// ---------------- generic GRU cell, batch 32 (x = [x1 | x2]) -----------------
__global__ void __launch_bounds__(256) cell_kernel(
    const float* __restrict__ x1, int k1, const float* __restrict__ x2, int k2,
    const float* __restrict__ h, const float* __restrict__ wih,
    const float* __restrict__ whh, const float* __restrict__ bih,
    const float* __restrict__ bhh, float* __restrict__ hout)
{
    const int b = blockIdx.x, tid = threadIdx.x;
    const int K = k1 + k2;
    __shared__ float xs[2304];
    __shared__ float hsm[HHH];
    __shared__ float gi[G3H], gh[G3H];
    for (int i = tid; i < k1; i += 256) xs[i] = x1[(size_t)b * k1 + i];
    for (int i = tid; i < k2; i += 256) xs[k1 + i] = x2[(size_t)b * k2 + i];
    hsm[tid] = h[b * HHH + tid];
    __syncthreads();
    for (int r = tid; r < G3H; r += 256) {
        const float4* wr = (const float4*)(wih + (size_t)r * K);
        float a0 = 0.f, a1 = 0.f, a2 = 0.f, a3 = 0.f;
        for (int q4 = 0; q4 < K / 4; ++q4) {
            float4 w = wr[q4];
            a0 += w.x * xs[4 * q4];     a1 += w.y * xs[4 * q4 + 1];
            a2 += w.z * xs[4 * q4 + 2]; a3 += w.w * xs[4 * q4 + 3];
        }
        gi[r] = bih[r] + (a0 + a1) + (a2 + a3);
        const float4* hr = (const float4*)(whh + (size_t)r * HHH);
        float c0 = 0.f, c1 = 0.f, c2 = 0.f, c3 = 0.f;
        for (int q4 = 0; q4 < HHH / 4; ++q4) {
            float4 w = hr[q4];
            c0 += w.x * hsm[4 * q4];     c1 += w.y * hsm[4 * q4 + 1];
            c2 += w.z * hsm[4 * q4 + 2]; c3 += w.w * hsm[4 * q4 + 3];
        }
        gh[r] = bhh[r] + (c0 + c1) + (c2 + c3);
    }
    __syncthreads();
    const int k = tid;
    float rg = 1.f / (1.f + expf(-(gi[k] + gh[k])));
    float zg = 1.f / (1.f + expf(-(gi[HHH + k] + gh[HHH + k])));
    float ng = tanhf(gi[2 * HHH + k] + rg * gh[2 * HHH + k]);
    hout[b * HHH + k] = (1.f - zg) * ng + zg * hsm[k];
}

// ---------------- logits[b][o] = msq[b] . out_w[o] + out_b[o] ----------------
__global__ void __launch_bounds__(256) logits_kernel(
    const float* __restrict__ hv, const float* __restrict__ ow,
    const float* __restrict__ ob, float* __restrict__ y)
{
    const int b = blockIdx.x, tid = threadIdx.x;
    __shared__ float ms[HHH];
    ms[tid] = hv[b * HHH + tid];
    __syncthreads();
    for (int o = tid; o < OOO; o += 256) {
        const float4* wr = (const float4*)(ow + (size_t)o * HHH);
        float a0 = 0.f, a1 = 0.f, a2 = 0.f, a3 = 0.f;
        #pragma unroll 8
        for (int k4 = 0; k4 < HHH / 4; ++k4) {
            float4 w = wr[k4];
            a0 += w.x * ms[4 * k4];     a1 += w.y * ms[4 * k4 + 1];
            a2 += w.z * ms[4 * k4 + 2]; a3 += w.w * ms[4 * k4 + 3];
        }
        y[(size_t)b * OOO + o] = ob[o] + (a0 + a1) + (a2 + a3);
    }
}

// ---------------- softmax over O=2000 ----------------------------------------
__global__ void __launch_bounds__(256) softmaxO_kernel(const float* __restrict__ yin,
                                                       float* __restrict__ yout)
{
    const int b = blockIdx.x, tid = threadIdx.x;
    __shared__ float red[8];
    float m = -1e30f;
    for (int o = tid; o < OOO; o += 256) m = fmaxf(m, yin[(size_t)b * OOO + o]);
    for (int o = 16; o; o >>= 1) m = fmaxf(m, __shfl_xor_sync(0xffffffffu, m, o));
    if ((tid & 31) == 0) red[tid >> 5] = m;
    __syncthreads();
    m = red[0];
    #pragma unroll
    for (int i = 1; i < 8; ++i) m = fmaxf(m, red[i]);
    __syncthreads();
    float sum = 0.f;
    for (int o = tid; o < OOO; o += 256) sum += expf(yin[(size_t)b * OOO + o] - m);
    for (int o = 16; o; o >>= 1) sum += __shfl_xor_sync(0xffffffffu, sum, o);
    if ((tid & 31) == 0) red[tid >> 5] = sum;
    __syncthreads();
    sum = 0.f;
    #pragma unroll
    for (int i = 0; i < 8; ++i) sum += red[i];
    float inv = 1.f / sum;
    for (int o = tid; o < OOO; o += 256)
        yout[(size_t)b * OOO + o] = expf(yin[(size_t)b * OOO + o] - m) * inv;
}

__global__ void copy_kernel(const float* __restrict__ s, float* __restrict__ d, int n)
{
    int i = blockIdx.x * 256 + threadIdx.x;
    if (i < n) d[i] = s[i];
}

// ------------------------------- launch --------------------------------------
extern "C" void kernel_launch(void* const* d_in, const int* in_sizes, int n_in,
                              void* d_out, int out_size)
{
    const float* c        = (const float*)d_in[0];
    const float* q        = (const float*)d_in[1];
    const float* i_state  = (const float*)d_in[2];
    const float* q_state  = (const float*)d_in[3];
    const float* in_w_ih  = (const float*)d_in[4];
    const float* in_w_hh  = (const float*)d_in[5];
    const float* in_b_ih  = (const float*)d_in[6];
    const float* in_b_hh  = (const float*)d_in[7];
    const float* qe_w_ih  = (const float*)d_in[8];
    const float* qe_w_hh  = (const float*)d_in[9];
    const float* qe_b_ih  = (const float*)d_in[10];
    const float* qe_b_hh  = (const float*)d_in[11];
    const float* att_weight = (const float*)d_in[12];
    const float* att_w1   = (const float*)d_in[13];
    const float* att_b1   = (const float*)d_in[14];
    const float* att_w2   = (const float*)d_in[15];
    const float* att_b2   = (const float*)d_in[16];
    const float* mem_w_ih = (const float*)d_in[17];
    const float* mem_w_hh = (const float*)d_in[18];
    const float* mem_b_ih = (const float*)d_in[19];
    const float* mem_b_hh = (const float*)d_in[20];
    const float* out_w    = (const float*)d_in[21];
    const float* out_b    = (const float*)d_in[22];
    const float* ans_w_ih = (const float*)d_in[23];
    const float* ans_w_hh = (const float*)d_in[24];
    const float* ans_b_ih = (const float*)d_in[25];
    const float* ans_b_hh = (const float*)d_in[26];
    const int*   c_index  = (const int*)d_in[27];
    const int*   len_c    = (const int*)d_in[28];
    float* out = (float*)d_out;

    float* gb = nullptr;
    cudaGetSymbolAddress((void**)&gb, g_buf);
    float* GI   = gb + OFF_GI;
    float* GIQ  = gb + OFF_GIQ;
    float* HB   = gb + OFF_H;
    float* COUT = gb + OFF_COUT;
    float* QOUT = gb + OFF_QOUT;
    float* QH   = gb + OFF_QH;
    float* HTC  = gb + OFF_HTC;
    float* CSEL = gb + OFF_CSEL;
    float* CW   = gb + OFF_CW;
    float* DOTQ = gb + OFF_DOTQ;
    float* DOTM = gb + OFF_DOTM;
    float* T0   = gb + OFF_T0;
    float* M    = gb + OFF_M;
    float* SC   = gb + OFF_SC;
    float* P    = gb + OFF_P;
    float* E    = gb + OFF_E;
    float* MSQ  = gb + OFF_MSQ;
    float* Y    = gb + OFF_Y;
    float* W1T  = gb + OFF_W1T;
    float* BT   = gb + OFF_BT;

    // ---- context GRU ----
    gi_kernel<<<SSL, 256>>>(c, in_w_ih, in_b_ih, GI, SSL);
    inith_kernel<<<BB, HHH>>>(i_state, HB);
    rec_kernel<<<128, 192>>>(GI, in_w_hh, in_b_hh, SSL, HB, COUT, HTC);

    // ---- query GRU ----
    gi_kernel<<<SQQ, 256>>>(q, qe_w_ih, qe_b_ih, GIQ, SQQ);
    inith_kernel<<<BB, HHH>>>(q_state, HB);
    rec_kernel<<<128, 192>>>(GIQ, qe_w_hh, qe_b_hh, SQQ, HB, QOUT, QH);

    // ---- attention prep ----
    w1t_kernel<<<(FEAT * 128 + 255) / 256, 256>>>(att_w1, W1T);
    cwgather_kernel<<<BB * NNN / 16, 256>>>(COUT, c_index, att_weight, CSEL, CW);
    dot_kernel<<<BB * NNN, 64>>>(CW, QH, DOTQ);
    bterm_kernel<<<BB, 128>>>(QH, att_w1, att_b1, 512, BT);
    attproj_kernel<true, false><<<BB * NNN / 16, 128>>>(
        CSEL, QH, nullptr, DOTQ, W1T, BT, 768, 1280, 1792, nullptr, nullptr, T0, nullptr);
    copy_kernel<<<(BB * HHH + 255) / 256, 256>>>(QH, M, BB * HHH);

    // ---- 3 memory hops ----
    for (int hop = 0; hop < 3; ++hop) {
        dot_kernel<<<BB * NNN, 64>>>(CW, M, DOTM);
        bterm_kernel<<<BB, 128>>>(M, att_w1, nullptr, 256, BT);
        attproj_kernel<false, true><<<BB * NNN / 16, 128>>>(
            CSEL, M, T0, DOTM, W1T, BT, 1024, 1536, 1793, att_w2, att_b2, nullptr, SC);
        softmaxN_kernel<<<BB, NNN>>>(SC, len_c, P, out + BB * OOO + hop * BB * NNN);
        e_kernel<<<BB, HHH>>>(CSEL, P, E);
        cell_kernel<<<BB, 256>>>(E, HHH, nullptr, 0, M,
                                 mem_w_ih, mem_w_hh, mem_b_ih, mem_b_hh, M);
    }

    // ---- answer loop ----
    copy_kernel<<<(BB * HHH + 255) / 256, 256>>>(M, MSQ, BB * HHH);
    for (int t = 0; t < 2; ++t) {
        logits_kernel<<<BB, 256>>>(MSQ, out_w, out_b, Y);
        softmaxO_kernel<<<BB, 256>>>(Y, Y);
        cell_kernel<<<BB, 256>>>(Y, OOO, QH, HHH, MSQ,
                                 ans_w_ih, ans_w_hh, ans_b_ih, ans_b_hh, MSQ);
    }
    logits_kernel<<<BB, 256>>>(MSQ, out_w, out_b, Y);
    softmaxO_kernel<<<BB, 256>>>(Y, out);   // y -> first 64000 floats of d_out
}